// round 8
// baseline (speedup 1.0000x reference)
#include <cuda_runtime.h>
#include <cuda_bf16.h>
#include <math.h>
#include <stdint.h>

// Problem constants
#define BB    64
#define CC    512
#define HH    8
#define HD    64
#define FREQE 256
#define ROWS  4096   // B*N == N*M

// ---------------------------------------------------------------------------
// Scratch (device globals; no allocation allowed)
// ---------------------------------------------------------------------------
__device__ float g_pe [ROWS * CC];
__device__ float g_q  [ROWS * CC];
__device__ float g_k  [ROWS * CC];
__device__ float g_v  [ROWS * CC];
__device__ float g_x  [ROWS * CC];      // attention output (tf32-rounded)
__device__ float g_emb[ROWS * FREQE];   // tf32-rounded
__device__ float g_hid[ROWS * CC];      // tf32-rounded
__device__ float g_qt [ROWS * CC];      // query tf32-rounded
__device__ float g_bqkv[3 * CC];
__device__ float g_wt [6 * CC * CC];    // tf32-rounded transposed W1,W2,Wq,Wk,Wv,Wo

__device__ __forceinline__ uint32_t to_tf32(float x) {
    uint32_t u;
    asm("cvt.rna.tf32.f32 %0, %1;" : "=r"(u) : "f"(x));
    return u;
}
__device__ __forceinline__ float round_tf32(float x) {
    return __uint_as_float(to_tf32(x));
}

__device__ __forceinline__ uint32_t smem_u32(const void* p) {
    uint32_t a;
    asm("{ .reg .u64 t; cvta.to.shared.u64 t, %1; cvt.u32.u64 %0, t; }"
        : "=r"(a) : "l"(p));
    return a;
}

__device__ __forceinline__ void cp16(uint32_t dst, const void* src) {
    asm volatile("cp.async.cg.shared.global [%0], [%1], 16;" :: "r"(dst), "l"(src));
}
#define CP_COMMIT() asm volatile("cp.async.commit_group;" ::: "memory")
#define CP_WAIT(n)  asm volatile("cp.async.wait_group %0;" :: "n"(n) : "memory")

// ---------------------------------------------------------------------------
// ONE prep kernel: flat grid, slot dispatch.
//   blocks [0, 4096)        : sinusoidal embedding -> g_emb (tf32)
//   blocks [4096, 12288)    : query round -> g_qt
//   blocks [12288, 13824)   : 6 weight transposes -> g_wt (tf32)
//   blocks [13824, 13830)   : fused qkv bias -> g_bqkv
// ---------------------------------------------------------------------------
#define PREP_BLOCKS (4096 + 8192 + 1536 + 6)

__global__ __launch_bounds__(256) void prep_kernel(
    const float* __restrict__ qpos, const float* __restrict__ query,
    const float* __restrict__ W1, const float* __restrict__ W2,
    const float* __restrict__ Wq, const float* __restrict__ Wk,
    const float* __restrict__ Wv, const float* __restrict__ Wo,
    const float* __restrict__ bq, const float* __restrict__ bv)
{
    int bid = blockIdx.x;
    int t = threadIdx.x;

    if (bid < 4096) {                       // embedding
        int idx = bid * 256 + t;
        int p = idx >> 8;
        int j = idx & 255;
        float tp = qpos[p];
        int jj = j & 127;
        float f = expf(-9.210340371976184f * (float)jj * (1.0f / 128.0f));
        float a = tp * f;
        float v = (j < 128) ? cosf(a) : sinf(a);
        g_emb[idx] = round_tf32(v);
        return;
    }
    if (bid < 12288) {                      // query rounding
        int idx = (bid - 4096) * 256 + t;
        g_qt[idx] = round_tf32(query[idx]);
        return;
    }
    if (bid < 13824) {                      // weight transposes
        int bid2 = bid - 12288;
        int slot = bid2 >> 8;               // 0..5
        int r    = bid2 & 255;
        int k0 = (r & 15) * 32;
        int n0 = (r >> 4) * 32;
        int K = (slot == 0) ? FREQE : CC;
        if (k0 >= K) return;

        const float* W = (slot == 0) ? W1 : (slot == 1) ? W2 : (slot == 2) ? Wq
                       : (slot == 3) ? Wk : (slot == 4) ? Wv : Wo;

        __shared__ float sm[32][33];
        int tx = t & 31, ty = t >> 5;
#pragma unroll
        for (int i = 0; i < 4; i++) {
            int rr = ty + i * 8;
            sm[rr][tx] = W[(size_t)(k0 + rr) * CC + n0 + tx];
        }
        __syncthreads();
#pragma unroll
        for (int i = 0; i < 4; i++) {
            int rr = ty + i * 8;
            g_wt[(size_t)slot * CC * CC + (size_t)(n0 + rr) * K + k0 + tx] =
                round_tf32(sm[tx][rr]);
        }
        return;
    }
    {                                       // bias fuse
        int i = (bid - 13824) * 256 + t;    // 0..1535
        float v = 0.0f;
        if (i < 512) v = bq[i];
        else if (i >= 1024) v = bv[i - 1024];
        g_bqkv[i] = v;
    }
}

// ---------------------------------------------------------------------------
// 1xTF32 GEMM, BM=64 x BN=128 x BK=32 tiles, 8 warps of 32x32.
// Inputs pre-rounded to tf32; inner loop loads raw bits.
// Grid: (N/128, M/64). 2 CTAs/SM co-resident (smem 54KB, regs < 128).
// epi: 0=+bias ; 1=silu(+bias),tf32 ; 2=+bias+resid ; 3=QKV split
// ---------------------------------------------------------------------------
#define TPAD 36
#define ATILE (64 * TPAD * 4)           // 9216 B
#define BTILE (128 * TPAD * 4)          // 18432 B
#define TSMEM (2 * ATILE + 2 * BTILE)   // 55296 B

#define MMA1688T(d, a, b) \
    asm volatile( \
        "mma.sync.aligned.m16n8k8.row.col.f32.tf32.tf32.f32 " \
        "{%0,%1,%2,%3}, {%4,%5,%6,%7}, {%8,%9}, {%0,%1,%2,%3};" \
        : "+f"((d)[0]), "+f"((d)[1]), "+f"((d)[2]), "+f"((d)[3]) \
        : "r"((a)[0]), "r"((a)[1]), "r"((a)[2]), "r"((a)[3]), \
          "r"((b)[0]), "r"((b)[1]))

__global__ __launch_bounds__(256, 2) void gemm_tf32(
    const float* __restrict__ A, const float* __restrict__ Bt,
    const float* __restrict__ bias, const float* __restrict__ resid,
    float* __restrict__ Cf, float* __restrict__ C2, float* __restrict__ C3,
    int K, int epi)
{
    extern __shared__ float smf[];
    uint32_t sbase = smem_u32(smf);

    int t = threadIdx.x, lane = t & 31, wid = t >> 5;
    int wm = wid >> 2;        // 0..1 -> m offset wm*32
    int wn = wid & 3;         // 0..3 -> n offset wn*32
    int m0 = blockIdx.y * 64, n0 = blockIdx.x * 128;
    int gr = lane >> 2, gc = lane & 3;

    float acc[2][4][4];
#pragma unroll
    for (int mi = 0; mi < 2; mi++)
#pragma unroll
        for (int ni = 0; ni < 4; ni++)
#pragma unroll
            for (int j = 0; j < 4; j++) acc[mi][ni][j] = 0.0f;

    int nch = K >> 5;

    auto load_chunk = [&](int ch, int buf) {
        int k0 = ch << 5;
        // A tile: 64 rows x 8 chunks = 512 float4 slots
#pragma unroll
        for (int i = 0; i < 2; i++) {
            int idx = t + i * 256;
            int row = idx >> 3;
            int c   = idx & 7;
            uint32_t off = (uint32_t)(row * TPAD * 4 + c * 16);
            cp16(sbase + buf * ATILE + off,
                 A + (size_t)(m0 + row) * K + k0 + c * 4);
        }
        // B tile: 128 rows x 8 chunks = 1024 slots
#pragma unroll
        for (int i = 0; i < 4; i++) {
            int idx = t + i * 256;
            int row = idx >> 3;
            int c   = idx & 7;
            uint32_t off = (uint32_t)(row * TPAD * 4 + c * 16);
            cp16(sbase + 2 * ATILE + buf * BTILE + off,
                 Bt + (size_t)(n0 + row) * K + k0 + c * 4);
        }
        CP_COMMIT();
    };

    load_chunk(0, 0);
    load_chunk(1, 1);

    for (int ch = 0; ch < nch; ch++) {
        if (ch + 1 < nch) { CP_WAIT(1); } else { CP_WAIT(0); }
        __syncthreads();

        int buf = ch & 1;
        const uint32_t* sA = (const uint32_t*)(smf + (buf * ATILE >> 2));
        const uint32_t* sB = (const uint32_t*)(smf + ((2 * ATILE + buf * BTILE) >> 2));

#pragma unroll
        for (int ks = 0; ks < 4; ks++) {
            int kk = ks * 8;
            uint32_t af[2][4], bf[4][2];
#pragma unroll
            for (int mi = 0; mi < 2; mi++) {
                int base = (wm * 32 + mi * 16 + gr) * TPAD + kk;
                af[mi][0] = sA[base + gc];
                af[mi][1] = sA[base + 8 * TPAD + gc];
                af[mi][2] = sA[base + gc + 4];
                af[mi][3] = sA[base + 8 * TPAD + gc + 4];
            }
#pragma unroll
            for (int ni = 0; ni < 4; ni++) {
                int base = (wn * 32 + ni * 8 + gr) * TPAD + kk;
                bf[ni][0] = sB[base + gc];
                bf[ni][1] = sB[base + gc + 4];
            }
#pragma unroll
            for (int mi = 0; mi < 2; mi++)
#pragma unroll
                for (int ni = 0; ni < 4; ni++)
                    MMA1688T(acc[mi][ni], af[mi], bf[ni]);
        }
        __syncthreads();
        if (ch + 2 < nch) load_chunk(ch + 2, buf);
    }

    // Epilogue
#pragma unroll
    for (int mi = 0; mi < 2; mi++) {
#pragma unroll
        for (int ni = 0; ni < 4; ni++) {
            int row0 = m0 + wm * 32 + mi * 16 + gr;
            int col  = n0 + wn * 32 + ni * 8 + gc * 2;
#pragma unroll
            for (int half = 0; half < 2; half++) {
                int row = row0 + half * 8;
                float v0 = acc[mi][ni][half * 2 + 0];
                float v1 = acc[mi][ni][half * 2 + 1];
                if (bias) { v0 += bias[col]; v1 += bias[col + 1]; }
                if (epi == 1) {
                    v0 = round_tf32(v0 / (1.0f + expf(-v0)));
                    v1 = round_tf32(v1 / (1.0f + expf(-v1)));
                }
                if (epi == 3) {
                    int seg = col >> 9;
                    float* dst = (seg == 0) ? Cf : (seg == 1) ? C2 : C3;
                    size_t o = (size_t)row * CC + (col & 511);
                    *(float2*)(dst + o) = make_float2(v0, v1);
                } else {
                    size_t o = (size_t)row * CC + col;
                    if (epi == 2) {
                        v0 += resid[o];
                        v1 += resid[o + 1];
                    }
                    *(float2*)(Cf + o) = make_float2(v0, v1);
                }
            }
        }
    }
}

// ---------------------------------------------------------------------------
// Fused attention, 4 batches per block: grid (16 bgroups, 8 heads).
// ---------------------------------------------------------------------------
#define ATTN_SMEM (4 * 64 * 68 * 4)

__global__ __launch_bounds__(256, 1) void attn_kernel() {
    extern __shared__ float kv[];      // staging: [4][64][68]
    __shared__ float qrow[4][64];
    __shared__ float s[4][64];

    int h   = blockIdx.y;
    int bg0 = blockIdx.x * 4;
    int t   = threadIdx.x;
    int bh  = t >> 6;
    int i   = t & 63;

    float kreg[64], vreg[64];

#pragma unroll
    for (int it = 0; it < 16; it++) {
        int slot = t + it * 256;
        int b  = slot >> 10;
        int m  = (slot >> 4) & 63;
        int d4 = slot & 15;
        float4 x = *(const float4*)(g_k + ((size_t)((bg0 + b) * 64 + m)) * 512 + h * 64 + d4 * 4);
        *(float4*)&kv[(b * 64 + m) * 68 + d4 * 4] = x;
    }
    __syncthreads();
#pragma unroll
    for (int d = 0; d < 64; d++) kreg[d] = kv[(bh * 64 + i) * 68 + d];
    __syncthreads();

#pragma unroll
    for (int it = 0; it < 16; it++) {
        int slot = t + it * 256;
        int b  = slot >> 10;
        int m  = (slot >> 4) & 63;
        int d4 = slot & 15;
        float4 x = *(const float4*)(g_v + ((size_t)((bg0 + b) * 64 + m)) * 512 + h * 64 + d4 * 4);
        *(float4*)&kv[(b * 64 + m) * 68 + d4 * 4] = x;
    }
    __syncthreads();
#pragma unroll
    for (int m = 0; m < 64; m++) vreg[m] = kv[(bh * 64 + m) * 68 + i];
    __syncthreads();

    for (int n = 0; n < 64; n++) {
        if (t < 64) {
            int b = t >> 4, w = t & 15;
            float4 qv = *(const float4*)(g_q + ((size_t)((bg0 + b) * 64 + n)) * 512 + h * 64 + w * 4);
            *(float4*)&qrow[b][w * 4] = qv;
        }
        __syncthreads();

        const float* pep = g_pe + ((size_t)(n * 64 + i)) * 512 + h * 64;
        float p = 0.0f;
#pragma unroll
        for (int d4 = 0; d4 < 16; d4++) {
            float4 pe4 = *(const float4*)(pep + d4 * 4);
            int d = d4 * 4;
            p = fmaf(qrow[bh][d + 0] * kreg[d + 0], pe4.x, p);
            p = fmaf(qrow[bh][d + 1] * kreg[d + 1], pe4.y, p);
            p = fmaf(qrow[bh][d + 2] * kreg[d + 2], pe4.z, p);
            p = fmaf(qrow[bh][d + 3] * kreg[d + 3], pe4.w, p);
        }
        s[bh][i] = p * 0.125f;
        __syncthreads();

        if (t < 128) {
            int w = t >> 5, lane = t & 31;
            float a  = s[w][lane];
            float c2 = s[w][lane + 32];
            float mx = fmaxf(a, c2);
#pragma unroll
            for (int off = 16; off > 0; off >>= 1)
                mx = fmaxf(mx, __shfl_xor_sync(0xffffffffu, mx, off));
            float e1 = __expf(a - mx), e2 = __expf(c2 - mx);
            float sm = e1 + e2;
#pragma unroll
            for (int off = 16; off > 0; off >>= 1)
                sm += __shfl_xor_sync(0xffffffffu, sm, off);
            float inv = 1.0f / sm;
            s[w][lane]      = e1 * inv;
            s[w][lane + 32] = e2 * inv;
        }
        __syncthreads();

        float xv = 0.0f;
#pragma unroll
        for (int m = 0; m < 64; m++)
            xv = fmaf(s[bh][m], vreg[m], xv);
        size_t o = ((size_t)((bg0 + bh) * 64 + n)) * 512 + h * 64 + i;
        g_x[o] = round_tf32(xv);
        __syncthreads();
    }
}

// ---------------------------------------------------------------------------
// Launch — 6 launches total:
//   main: prep ─ew─┬─ s1: MLP1 ─ MLP2 ─e1─┐
//                  └─ s2: QKV ─e2─────────┼─ attn ─ out (main)
// ---------------------------------------------------------------------------
extern "C" void kernel_launch(void* const* d_in, const int* in_sizes, int n_in,
                              void* d_out, int out_size)
{
    const float* query = (const float*)d_in[0];
    const float* qpos  = (const float*)d_in[1];
    const float* Wq    = (const float*)d_in[2];
    const float* bq    = (const float*)d_in[3];
    const float* Wk    = (const float*)d_in[4];
    const float* Wv    = (const float*)d_in[5];
    const float* bv    = (const float*)d_in[6];
    const float* Wo    = (const float*)d_in[7];
    const float* bo    = (const float*)d_in[8];
    const float* W1    = (const float*)d_in[9];
    const float* b1    = (const float*)d_in[10];
    const float* W2    = (const float*)d_in[11];
    const float* b2    = (const float*)d_in[12];
    float* out = (float*)d_out;

    static cudaStream_t s1 = nullptr, s2 = nullptr;
    static cudaEvent_t ew = nullptr, e1 = nullptr, e2 = nullptr;
    if (!s1) {
        cudaStreamCreateWithFlags(&s1, cudaStreamNonBlocking);
        cudaStreamCreateWithFlags(&s2, cudaStreamNonBlocking);
        cudaEventCreateWithFlags(&ew, cudaEventDisableTiming);
        cudaEventCreateWithFlags(&e1, cudaEventDisableTiming);
        cudaEventCreateWithFlags(&e2, cudaEventDisableTiming);
        cudaFuncSetAttribute(gemm_tf32, cudaFuncAttributeMaxDynamicSharedMemorySize, TSMEM);
        cudaFuncSetAttribute(attn_kernel, cudaFuncAttributeMaxDynamicSharedMemorySize, ATTN_SMEM);
    }

    void *p_pe, *p_q, *p_k, *p_v, *p_x, *p_bqkv, *p_emb, *p_hid, *p_qt, *p_wt;
    cudaGetSymbolAddress(&p_pe,   g_pe);
    cudaGetSymbolAddress(&p_q,    g_q);
    cudaGetSymbolAddress(&p_k,    g_k);
    cudaGetSymbolAddress(&p_v,    g_v);
    cudaGetSymbolAddress(&p_x,    g_x);
    cudaGetSymbolAddress(&p_bqkv, g_bqkv);
    cudaGetSymbolAddress(&p_emb,  g_emb);
    cudaGetSymbolAddress(&p_hid,  g_hid);
    cudaGetSymbolAddress(&p_qt,   g_qt);
    cudaGetSymbolAddress(&p_wt,   g_wt);

    const float* wt = (const float*)p_wt;
    const int WSLOT = CC * CC;

    // launch 1: all prep (embed, qround, wconv, bias)
    prep_kernel<<<PREP_BLOCKS, 256>>>(qpos, query, W1, W2, Wq, Wk, Wv, Wo, bq, bv);
    cudaEventRecord(ew, 0);

    // s1: pe MLP
    cudaStreamWaitEvent(s1, ew, 0);
    gemm_tf32<<<dim3(4, 64), 256, TSMEM, s1>>>(
        (const float*)p_emb, wt + 0 * WSLOT, b1, nullptr,
        (float*)p_hid, nullptr, nullptr, FREQE, 1);
    gemm_tf32<<<dim3(4, 64), 256, TSMEM, s1>>>(
        (const float*)p_hid, wt + 1 * WSLOT, b2, nullptr,
        (float*)p_pe, nullptr, nullptr, CC, 0);
    cudaEventRecord(e1, s1);

    // s2: fused QKV
    cudaStreamWaitEvent(s2, ew, 0);
    gemm_tf32<<<dim3(12, 64), 256, TSMEM, s2>>>(
        (const float*)p_qt, wt + 2 * WSLOT, (const float*)p_bqkv, nullptr,
        (float*)p_q, (float*)p_k, (float*)p_v, CC, 3);
    cudaEventRecord(e2, s2);

    // join -> attention -> output projection (+bias +residual)
    cudaStreamWaitEvent(0, e1, 0);
    cudaStreamWaitEvent(0, e2, 0);
    attn_kernel<<<dim3(16, HH), 256, ATTN_SMEM>>>();
    gemm_tf32<<<dim3(4, 64), 256, TSMEM>>>(
        (const float*)p_x, wt + 5 * WSLOT, bo, query,
        out, nullptr, nullptr, CC, 2);
}